// round 12
// baseline (speedup 1.0000x reference)
#include <cuda_runtime.h>
#include <math.h>

#define B 64
#define H 128
#define E 128
#define NL 4
#define S 8192
#define V 50257
#define FOURH 512
#define CHUNKS 128   // S / ROWS
#define ROWS 64

#define SZ_LOGITS (B*V)
#define OFF_C  (SZ_LOGITS)
#define OFF_H  (OFF_C + NL*B*H)
#define OFF_ATTN (OFF_H + NL*B*H)

typedef unsigned long long ull;

// ---------------- device scratch (no allocations allowed) ----------------
__device__ __align__(16) float g_x[B*H];          // final hidden (x)
__device__ __align__(16) float g_r[B*H];          // Wk @ q  per batch
__device__ float g_cK[B];                          // bk . q
__device__ float g_pl[B*CHUNKS];                   // partial exp-sums
__device__ __align__(16) float g_pacc[B*CHUNKS*H]; // partial weighted sums
__device__ __align__(16) float g_hln[B*H];
__device__ int g_cnt[B];                           // per-batch done counters

__device__ __forceinline__ float warp_sum(float v) {
#pragma unroll
    for (int o = 16; o > 0; o >>= 1) v += __shfl_xor_sync(0xffffffffu, v, o);
    return v;
}
__device__ __forceinline__ float sigf(float x) { return 1.f / (1.f + __expf(-x)); }

__device__ __forceinline__ ull fma2(ull a, ull b, ull c) {
    ull d;
    asm("fma.rn.f32x2 %0, %1, %2, %3;" : "=l"(d) : "l"(a), "l"(b), "l"(c));
    return d;
}
__device__ __forceinline__ ull bcast2(float f) {
    ull d;
    asm("mov.b64 %0, {%1, %1};" : "=l"(d) : "f"(f));
    return d;
}

// ============ K1: embed + 4-layer LSTM + q, r = Wk@q, cK = bk.q ============
// 32 blocks x 256 threads, 2 batches per block, f32x2 FMAs.
// Also resets g_cnt for this launch (hi-stream-serialized before k_active).
__global__ __launch_bounds__(256) void k_lstm(
    const int* __restrict__ token_id, const float* __restrict__ c0,
    const float* __restrict__ h0, const float* __restrict__ emb,
    const float* __restrict__ Wi, const float* __restrict__ Uh,
    const float* __restrict__ bL, const float* __restrict__ Wq,
    const float* __restrict__ bq, const float* __restrict__ Wk,
    const float* __restrict__ bk, float* __restrict__ out)
{
    __shared__ ull xs2[2][H];              // {x,x} broadcast pairs
    __shared__ ull hs2[2][H];              // {h,h} broadcast pairs
    __shared__ float gp[2][2][FOURH];      // [k-half][bb][col]
    __shared__ float qs[2][H];

    int tid = threadIdx.x;
    int b0 = blockIdx.x * 2;

    if (tid == 0) { g_cnt[b0] = 0; g_cnt[b0+1] = 0; }

    for (int idx = tid; idx < 2*H; idx += 256) {
        int bb = idx >> 7, i = idx & 127;
        float v = emb[(size_t)token_id[b0+bb]*E + i];
        xs2[bb][i] = bcast2(v);
    }

    int khalf = tid >> 7;        // 0 or 1: which half of k
    int tc = tid & 127;          // column group: cols [4tc, 4tc+4)
    int cbase = tc * 4;

    for (int l = 0; l < NL; l++) {
        for (int idx = tid; idx < 2*H; idx += 256) {
            int bb = idx >> 7, i = idx & 127;
            float v = h0[((size_t)l*B + b0 + bb)*H + i];
            hs2[bb][i] = bcast2(v);
        }
        __syncthreads();

        ull a00 = 0, a01 = 0, a10 = 0, a11 = 0;
        const ulonglong2* Wi2 = (const ulonglong2*)(Wi + (size_t)l*E*FOURH);
        const ulonglong2* Uh2 = (const ulonglong2*)(Uh + (size_t)l*H*FOURH);
        int k0 = khalf * 64;
#pragma unroll 4
        for (int k = k0; k < k0 + 64; k++) {
            ulonglong2 w = Wi2[k*(FOURH/4) + tc];
            ulonglong2 u = Uh2[k*(FOURH/4) + tc];
            ull x0 = xs2[0][k], x1 = xs2[1][k];
            ull hh0 = hs2[0][k], hh1 = hs2[1][k];
            a00 = fma2(w.x, x0, a00);  a01 = fma2(w.y, x0, a01);
            a00 = fma2(u.x, hh0, a00); a01 = fma2(u.y, hh0, a01);
            a10 = fma2(w.x, x1, a10);  a11 = fma2(w.y, x1, a11);
            a10 = fma2(u.x, hh1, a10); a11 = fma2(u.y, hh1, a11);
        }
        *(ull*)&gp[khalf][0][cbase]   = a00;
        *(ull*)&gp[khalf][0][cbase+2] = a01;
        *(ull*)&gp[khalf][1][cbase]   = a10;
        *(ull*)&gp[khalf][1][cbase+2] = a11;
        __syncthreads();

        // activations: 256 outputs (2 batches x 128)
        {
            int bb = tid >> 7, i = tid & 127;
            const float* bb_l = bL + l*FOURH;
            float ig = gp[0][bb][i]       + gp[1][bb][i]       + bb_l[i];
            float fg = gp[0][bb][128 + i] + gp[1][bb][128 + i] + bb_l[128 + i];
            float gg = gp[0][bb][256 + i] + gp[1][bb][256 + i] + bb_l[256 + i];
            float og = gp[0][bb][384 + i] + gp[1][bb][384 + i] + bb_l[384 + i];
            size_t ofs = ((size_t)l*B + b0 + bb)*H + i;
            float cprev = c0[ofs];
            float cn = sigf(fg)*cprev + sigf(ig)*tanhf(gg);
            float hn = sigf(og)*tanhf(cn);
            out[OFF_C + ofs] = cn;
            out[OFF_H + ofs] = hn;
            xs2[bb][i] = bcast2(hn);   // next-layer input; guarded by sync at loop top
        }
    }
    __syncthreads();

    for (int idx = tid; idx < 2*H; idx += 256) {
        int bb = idx >> 7, i = idx & 127;
        g_x[(b0+bb)*H + i] = ((const float2*)&xs2[bb][i])->x;
    }

    // q[bb][j] = x . Wq[:,j] + bq[j]
    {
        int bb = tid >> 7, j = tid & 127;
        float acc = bq[j];
#pragma unroll 8
        for (int i = 0; i < H; i++)
            acc += ((const float2*)&xs2[bb][i])->x * Wq[i*H + j];
        qs[bb][j] = acc;
    }
    __syncthreads();

    // r[bb][i] = Wk[i,:] . q[bb]  (warp per row)
    int wid = tid >> 5, lane = tid & 31;
    for (int row = wid; row < 2*H; row += 8) {
        int bb = row >> 7, i = row & 127;
        float4 wv = ((const float4*)(Wk + (size_t)i*H))[lane];
        float4 qv = ((const float4*)qs[bb])[lane];
        float d = wv.x*qv.x + wv.y*qv.y + wv.z*qv.z + wv.w*qv.w;
        d = warp_sum(d);
        if (lane == 0) g_r[(b0+bb)*H + i] = d;
    }
    if (wid < 2) {
        int bb = wid;
        float p = 0.f;
        for (int j = lane; j < H; j += 32) p += bk[j] * qs[bb][j];
        p = warp_sum(p);
        if (lane == 0) g_cK[b0+bb] = p;
    }
}

// ============ inline reduce for one batch (last-done block runs this) =====
__device__ __noinline__ void reduce_batch(
    int b, int nact,
    float* s_red, float* s_part, float* s_cp, float* s_xsm, float* s_ctx,
    const float* __restrict__ Wv, const float* __restrict__ bv,
    const float* __restrict__ Wmix, const float* __restrict__ bmix,
    const float* __restrict__ lns, const float* __restrict__ lnb)
{
    int tid = threadIdx.x;
    int t = tid & 127, half = tid >> 7;

    if (tid < 128)
        s_red[tid] = (tid < nact) ? g_pl[b*CHUNKS + tid] : 0.f;
    __syncthreads();
    for (int o = 64; o > 0; o >>= 1) {
        if (tid < o) s_red[tid] += s_red[tid+o];
        __syncthreads();
    }
    float L = s_red[0];
    __syncthreads();

    {
        float a = 0.f;
#pragma unroll 4
        for (int c = half; c < nact; c += 2)
            a += g_pacc[((size_t)b*CHUNKS + c)*H + t];
        s_part[tid] = a;
    }
    __syncthreads();
    if (tid < 128) {
        s_cp[t] = (s_part[t] + s_part[t+128]) / L;
        s_xsm[t] = g_x[b*H + t];
    }
    __syncthreads();

    {
        float cv = 0.f;
        int i0 = half*64;
#pragma unroll 8
        for (int i = i0; i < i0 + 64; i++) cv += s_cp[i] * Wv[i*H + t];
        s_part[tid] = cv;
    }
    __syncthreads();
    if (tid < 128) s_ctx[t] = s_part[t] + s_part[t+128] + bv[t];
    __syncthreads();

    {
        float hm = 0.f;
        if (half == 0) {
#pragma unroll 8
            for (int i = 0; i < 128; i++) hm += s_xsm[i] * Wmix[i*H + t];
        } else {
#pragma unroll 8
            for (int i = 0; i < 128; i++) hm += s_ctx[i] * Wmix[(H+i)*H + t];
        }
        s_part[tid] = hm;
    }
    __syncthreads();

    float hv = 0.f;
    if (tid < 128) {
        hv = tanhf(s_part[t] + s_part[t+128] + bmix[t]);
        s_red[t] = hv;
    }
    __syncthreads();
    for (int o = 64; o > 0; o >>= 1) {
        if (tid < o) s_red[tid] += s_red[tid+o];
        __syncthreads();
    }
    float mu = s_red[0] * (1.f/128.f);
    __syncthreads();
    float dv = hv - mu;
    if (tid < 128) s_red[t] = dv*dv;
    __syncthreads();
    for (int o = 64; o > 0; o >>= 1) {
        if (tid < o) s_red[tid] += s_red[tid+o];
        __syncthreads();
    }
    float var = s_red[0] * (1.f/128.f);

    if (tid < 128)
        g_hln[b*H + t] = dv * rsqrtf(var + 1e-6f) * lns[t] + lnb[t];
}

// ==== K2a: ACTIVE region copy + flash pass + inline per-batch reduce ======
// grid (CHUNKS, B); inactive chunks early-exit (handled by k_inactive).
__global__ __launch_bounds__(256) void k_active(
    const float* __restrict__ attn_mem, const int* __restrict__ step_p,
    const float* __restrict__ Wv, const float* __restrict__ bv,
    const float* __restrict__ Wmix, const float* __restrict__ bmix,
    const float* __restrict__ lns, const float* __restrict__ lnb,
    float* __restrict__ out)
{
    __shared__ float sm_acc[8][H];
    __shared__ float sm_l[8];
    __shared__ int sm_last;
    __shared__ float s_red[128], s_part[256], s_cp[H], s_xsm[H], s_ctx[H];

    int b = blockIdx.y;
    int chunk = blockIdx.x;
    int step = *step_p;
    if (chunk*ROWS > step) return;      // inactive -> other kernel

    int tid = threadIdx.x, wid = tid >> 5, lane = tid & 31;
    int base = chunk*ROWS + wid*8;

    const float4* src = (const float4*)(attn_mem + (size_t)b*S*H);
    float4* dst = (float4*)(out + OFF_ATTN + (size_t)b*S*H);
    const float4* xr = (const float4*)(g_x + b*H);
    float4 rf = ((const float4*)(g_r + b*H))[lane];
    float cK = g_cK[b];
    const float scl = 0.08838834764831843f;   // 1/sqrt(128)

    float4 v[8];
#pragma unroll
    for (int t = 0; t < 8; t++) {
        int s = base + t;
        v[t] = (s == step) ? xr[lane] : __ldcs(&src[(size_t)s*32 + lane]);
    }
#pragma unroll
    for (int t = 0; t < 8; t++) __stcs(&dst[(size_t)(base+t)*32 + lane], v[t]);

    // 8 independent partial dots, then 8 interleaved butterfly reductions
    float d[8];
#pragma unroll
    for (int t = 0; t < 8; t++)
        d[t] = v[t].x*rf.x + v[t].y*rf.y + v[t].z*rf.z + v[t].w*rf.w;
#pragma unroll
    for (int o = 16; o > 0; o >>= 1) {
#pragma unroll
        for (int t = 0; t < 8; t++)
            d[t] += __shfl_xor_sync(0xffffffffu, d[t], o);
    }

    // no-max softmax partials: scores are O(1), fp32 exp is safe
    float l = 0.f;
    float4 acc = {0.f, 0.f, 0.f, 0.f};
#pragma unroll
    for (int t = 0; t < 8; t++) {
        float w = (base + t <= step) ? __expf((d[t] + cK) * scl) : 0.f;
        l += w;
        acc.x += w*v[t].x; acc.y += w*v[t].y;
        acc.z += w*v[t].z; acc.w += w*v[t].w;
    }
    ((float4*)sm_acc[wid])[lane] = acc;
    if (lane == 0) sm_l[wid] = l;
    __syncthreads();

    if (tid < H) {
        float a = 0.f;
#pragma unroll
        for (int w = 0; w < 8; w++) a += sm_acc[w][tid];
        g_pacc[((size_t)b*CHUNKS + chunk)*H + tid] = a;
    }
    if (tid == 0) {
        float L = 0.f;
#pragma unroll
        for (int w = 0; w < 8; w++) L += sm_l[w];
        g_pl[b*CHUNKS + chunk] = L;
    }

    int nact = (step >> 6) + 1;
    __threadfence();                 // publish pacc/pl
    __syncthreads();
    if (tid == 0) {
        int old = atomicAdd(&g_cnt[b], 1);
        sm_last = (old == nact - 1);
    }
    __syncthreads();
    if (sm_last) {
        __threadfence();             // acquire
        reduce_batch(b, nact, s_red, s_part, s_cp, s_xsm, s_ctx,
                     Wv, bv, Wmix, bmix, lns, lnb);
    }
}

// ==== K2b: INACTIVE region pure streaming copy (no dependencies) ==========
__global__ __launch_bounds__(256) void k_inactive(
    const float* __restrict__ attn_mem, const int* __restrict__ step_p,
    float* __restrict__ out)
{
    int b = blockIdx.y;
    int chunk = blockIdx.x;
    int step = *step_p;
    if (chunk*ROWS <= step) return;     // active -> other kernel

    int tid = threadIdx.x, wid = tid >> 5, lane = tid & 31;
    int base = chunk*ROWS + wid*8;
    const float4* src = (const float4*)(attn_mem + (size_t)b*S*H);
    float4* dst = (float4*)(out + OFF_ATTN + (size_t)b*S*H);

    float4 v[8];
#pragma unroll
    for (int t = 0; t < 8; t++) v[t] = __ldcs(&src[(size_t)(base+t)*32 + lane]);
#pragma unroll
    for (int t = 0; t < 8; t++) __stcs(&dst[(size_t)(base+t)*32 + lane], v[t]);
}

// ==== K4: logits = h_ln @ Wout + bout; 2 cols (c, c+256) x 16 batches =====
__global__ __launch_bounds__(256, 3) void k_logits(
    const float* __restrict__ Wout, const float* __restrict__ bout,
    float* __restrict__ out)
{
    __shared__ ull hsu[H*8];   // [k][batch-pair]: 8KB
    int tid = threadIdx.x;
    int bq = blockIdx.y;       // batches [bq*16, bq*16+16)
    float* hsf = (float*)hsu;
    for (int idx = tid; idx < 16*H; idx += 256) {
        int k = idx >> 4, bb = idx & 15;
        hsf[k*16 + bb] = g_hln[(bq*16 + bb)*H + k];
    }
    __syncthreads();

    int base = blockIdx.x * 512;
    int ca = base + tid;            // column A
    int cb = ca + 256;              // column B
    int ca_ok = (ca < V), cb_ok = (cb < V);
    int ca_c = ca_ok ? ca : (V-1);
    int cb_c = cb_ok ? cb : (V-1);

    ull acc0[8], acc1[8];
#pragma unroll
    for (int i = 0; i < 8; i++) { acc0[i] = 0ULL; acc1[i] = 0ULL; }

#pragma unroll 4
    for (int k = 0; k < H; k++) {
        float wa = Wout[(size_t)k*V + ca_c];
        float wb = Wout[(size_t)k*V + cb_c];
        ull w2a = bcast2(wa);
        ull w2b = bcast2(wb);
        const ulonglong2* hp = (const ulonglong2*)(hsu + k*8);
#pragma unroll
        for (int p = 0; p < 4; p++) {
            ulonglong2 hv = hp[p];
            acc0[2*p]   = fma2(hv.x, w2a, acc0[2*p]);
            acc0[2*p+1] = fma2(hv.y, w2a, acc0[2*p+1]);
            acc1[2*p]   = fma2(hv.x, w2b, acc1[2*p]);
            acc1[2*p+1] = fma2(hv.y, w2b, acc1[2*p+1]);
        }
    }

    if (ca_ok) {
        float bo = bout[ca_c];
#pragma unroll
        for (int p = 0; p < 8; p++) {
            float f0, f1;
            asm("mov.b64 {%0, %1}, %2;" : "=f"(f0), "=f"(f1) : "l"(acc0[p]));
            int b0r = bq*16 + 2*p;
            out[(size_t)b0r*V + ca]     = f0 + bo;
            out[(size_t)(b0r+1)*V + ca] = f1 + bo;
        }
    }
    if (cb_ok) {
        float bo = bout[cb_c];
#pragma unroll
        for (int p = 0; p < 8; p++) {
            float f0, f1;
            asm("mov.b64 {%0, %1}, %2;" : "=f"(f0), "=f"(f1) : "l"(acc1[p]));
            int b0r = bq*16 + 2*p;
            out[(size_t)b0r*V + cb]     = f0 + bo;
            out[(size_t)(b0r+1)*V + cb] = f1 + bo;
        }
    }
}

// ---------------- streams/events created at static-init -------------------
static cudaStream_t g_hi, g_lo;
static cudaEvent_t  g_fork, g_join_hi, g_join_lo;
static struct StreamInit {
    StreamInit() {
        int least, greatest;
        cudaDeviceGetStreamPriorityRange(&least, &greatest);
        cudaStreamCreateWithPriority(&g_hi, cudaStreamNonBlocking, greatest);
        cudaStreamCreateWithPriority(&g_lo, cudaStreamNonBlocking, least);
        cudaEventCreateWithFlags(&g_fork, cudaEventDisableTiming);
        cudaEventCreateWithFlags(&g_join_hi, cudaEventDisableTiming);
        cudaEventCreateWithFlags(&g_join_lo, cudaEventDisableTiming);
    }
} g_stream_init;

// ==========================================================================
extern "C" void kernel_launch(void* const* d_in, const int* in_sizes, int n_in,
                              void* d_out, int out_size)
{
    const int*   token_id = (const int*)  d_in[0];
    const float* c0       = (const float*)d_in[1];
    const float* h0       = (const float*)d_in[2];
    const float* attn_mem = (const float*)d_in[3];
    const int*   step_p   = (const int*)  d_in[4];
    const float* emb      = (const float*)d_in[5];
    const float* Wi       = (const float*)d_in[6];
    const float* Uh       = (const float*)d_in[7];
    const float* bL       = (const float*)d_in[8];
    const float* Wq       = (const float*)d_in[9];
    const float* bq       = (const float*)d_in[10];
    const float* Wk       = (const float*)d_in[11];
    const float* bk       = (const float*)d_in[12];
    const float* Wv       = (const float*)d_in[13];
    const float* bv       = (const float*)d_in[14];
    const float* Wmix     = (const float*)d_in[15];
    const float* bmix     = (const float*)d_in[16];
    const float* lns      = (const float*)d_in[17];
    const float* lnb      = (const float*)d_in[18];
    const float* Wout     = (const float*)d_in[19];
    const float* bout     = (const float*)d_in[20];
    float* out = (float*)d_out;

    dim3 g2(CHUNKS, B);
    dim3 g4((V + 511)/512, 4);

    // fork both worker streams off the capture stream
    cudaEventRecord(g_fork, 0);
    cudaStreamWaitEvent(g_lo, g_fork, 0);
    cudaStreamWaitEvent(g_hi, g_fork, 0);

    // LOW priority: inactive-region copy (no deps; soaks idle bandwidth)
    k_inactive<<<g2, 256, 0, g_lo>>>(attn_mem, step_p, out);
    cudaEventRecord(g_join_lo, g_lo);

    // HIGH priority: lstm -> active copy+flash(+reduce) -> logits
    k_lstm<<<32, 256, 0, g_hi>>>(token_id, c0, h0, emb, Wi, Uh, bL,
                                 Wq, bq, Wk, bk, out);
    k_active<<<g2, 256, 0, g_hi>>>(attn_mem, step_p, Wv, bv, Wmix, bmix,
                                   lns, lnb, out);
    k_logits<<<g4, 256, 0, g_hi>>>(Wout, bout, out);
    cudaEventRecord(g_join_hi, g_hi);

    // join both chains back onto the capture stream
    cudaStreamWaitEvent(0, g_join_lo, 0);
    cudaStreamWaitEvent(0, g_join_hi, 0);
}

// round 13
// speedup vs baseline: 1.3002x; 1.3002x over previous
#include <cuda_runtime.h>
#include <math.h>

#define B 64
#define H 128
#define E 128
#define NL 4
#define S 8192
#define V 50257
#define FOURH 512
#define CHUNKS 128   // S / ROWS
#define ROWS 64

#define SZ_LOGITS (B*V)
#define OFF_C  (SZ_LOGITS)
#define OFF_H  (OFF_C + NL*B*H)
#define OFF_ATTN (OFF_H + NL*B*H)

typedef unsigned long long ull;

// ---------------- device scratch (no allocations allowed) ----------------
__device__ __align__(16) float g_x[B*H];          // final hidden (x)
__device__ __align__(16) float g_r[B*H];          // Wk @ q  per batch
__device__ float g_cK[B];                          // bk . q
__device__ float g_pl[B*CHUNKS];                   // partial exp-sums
__device__ __align__(16) float g_pacc[B*CHUNKS*H]; // partial weighted sums
__device__ __align__(16) float g_hln[B*H];
__device__ int g_cnt[B];                           // per-batch done counters

__device__ __forceinline__ float warp_sum(float v) {
#pragma unroll
    for (int o = 16; o > 0; o >>= 1) v += __shfl_xor_sync(0xffffffffu, v, o);
    return v;
}
__device__ __forceinline__ float sigf(float x) { return 1.f / (1.f + __expf(-x)); }

__device__ __forceinline__ ull fma2(ull a, ull b, ull c) {
    ull d;
    asm("fma.rn.f32x2 %0, %1, %2, %3;" : "=l"(d) : "l"(a), "l"(b), "l"(c));
    return d;
}
__device__ __forceinline__ ull bcast2(float f) {
    ull d;
    asm("mov.b64 %0, {%1, %1};" : "=l"(d) : "f"(f));
    return d;
}

// ============ K1: embed + 4-layer LSTM + q, r = Wk@q, cK = bk.q ============
// 32 blocks x 256 threads, 2 batches per block, f32x2 FMAs.
// Also resets g_cnt for this launch (hi-stream-serialized before k_active).
__global__ __launch_bounds__(256) void k_lstm(
    const int* __restrict__ token_id, const float* __restrict__ c0,
    const float* __restrict__ h0, const float* __restrict__ emb,
    const float* __restrict__ Wi, const float* __restrict__ Uh,
    const float* __restrict__ bL, const float* __restrict__ Wq,
    const float* __restrict__ bq, const float* __restrict__ Wk,
    const float* __restrict__ bk, float* __restrict__ out)
{
    __shared__ ull xs2[2][H];              // {x,x} broadcast pairs
    __shared__ ull hs2[2][H];              // {h,h} broadcast pairs
    __shared__ float gp[2][2][FOURH];      // [k-half][bb][col]
    __shared__ float qs[2][H];

    int tid = threadIdx.x;
    int b0 = blockIdx.x * 2;

    if (tid == 0) { g_cnt[b0] = 0; g_cnt[b0+1] = 0; }

    for (int idx = tid; idx < 2*H; idx += 256) {
        int bb = idx >> 7, i = idx & 127;
        float v = emb[(size_t)token_id[b0+bb]*E + i];
        xs2[bb][i] = bcast2(v);
    }

    int khalf = tid >> 7;        // 0 or 1: which half of k
    int tc = tid & 127;          // column group: cols [4tc, 4tc+4)
    int cbase = tc * 4;

    for (int l = 0; l < NL; l++) {
        for (int idx = tid; idx < 2*H; idx += 256) {
            int bb = idx >> 7, i = idx & 127;
            float v = h0[((size_t)l*B + b0 + bb)*H + i];
            hs2[bb][i] = bcast2(v);
        }
        __syncthreads();

        ull a00 = 0, a01 = 0, a10 = 0, a11 = 0;
        const ulonglong2* Wi2 = (const ulonglong2*)(Wi + (size_t)l*E*FOURH);
        const ulonglong2* Uh2 = (const ulonglong2*)(Uh + (size_t)l*H*FOURH);
        int k0 = khalf * 64;
#pragma unroll 4
        for (int k = k0; k < k0 + 64; k++) {
            ulonglong2 w = Wi2[k*(FOURH/4) + tc];
            ulonglong2 u = Uh2[k*(FOURH/4) + tc];
            ull x0 = xs2[0][k], x1 = xs2[1][k];
            ull hh0 = hs2[0][k], hh1 = hs2[1][k];
            a00 = fma2(w.x, x0, a00);  a01 = fma2(w.y, x0, a01);
            a00 = fma2(u.x, hh0, a00); a01 = fma2(u.y, hh0, a01);
            a10 = fma2(w.x, x1, a10);  a11 = fma2(w.y, x1, a11);
            a10 = fma2(u.x, hh1, a10); a11 = fma2(u.y, hh1, a11);
        }
        *(ull*)&gp[khalf][0][cbase]   = a00;
        *(ull*)&gp[khalf][0][cbase+2] = a01;
        *(ull*)&gp[khalf][1][cbase]   = a10;
        *(ull*)&gp[khalf][1][cbase+2] = a11;
        __syncthreads();

        // activations: 256 outputs (2 batches x 128)
        {
            int bb = tid >> 7, i = tid & 127;
            const float* bb_l = bL + l*FOURH;
            float ig = gp[0][bb][i]       + gp[1][bb][i]       + bb_l[i];
            float fg = gp[0][bb][128 + i] + gp[1][bb][128 + i] + bb_l[128 + i];
            float gg = gp[0][bb][256 + i] + gp[1][bb][256 + i] + bb_l[256 + i];
            float og = gp[0][bb][384 + i] + gp[1][bb][384 + i] + bb_l[384 + i];
            size_t ofs = ((size_t)l*B + b0 + bb)*H + i;
            float cprev = c0[ofs];
            float cn = sigf(fg)*cprev + sigf(ig)*tanhf(gg);
            float hn = sigf(og)*tanhf(cn);
            out[OFF_C + ofs] = cn;
            out[OFF_H + ofs] = hn;
            xs2[bb][i] = bcast2(hn);   // next-layer input; guarded by sync at loop top
        }
    }
    __syncthreads();

    for (int idx = tid; idx < 2*H; idx += 256) {
        int bb = idx >> 7, i = idx & 127;
        g_x[(b0+bb)*H + i] = ((const float2*)&xs2[bb][i])->x;
    }

    // q[bb][j] = x . Wq[:,j] + bq[j]
    {
        int bb = tid >> 7, j = tid & 127;
        float acc = bq[j];
#pragma unroll 8
        for (int i = 0; i < H; i++)
            acc += ((const float2*)&xs2[bb][i])->x * Wq[i*H + j];
        qs[bb][j] = acc;
    }
    __syncthreads();

    // r[bb][i] = Wk[i,:] . q[bb]  (warp per row)
    int wid = tid >> 5, lane = tid & 31;
    for (int row = wid; row < 2*H; row += 8) {
        int bb = row >> 7, i = row & 127;
        float4 wv = ((const float4*)(Wk + (size_t)i*H))[lane];
        float4 qv = ((const float4*)qs[bb])[lane];
        float d = wv.x*qv.x + wv.y*qv.y + wv.z*qv.z + wv.w*qv.w;
        d = warp_sum(d);
        if (lane == 0) g_r[(b0+bb)*H + i] = d;
    }
    if (wid < 2) {
        int bb = wid;
        float p = 0.f;
        for (int j = lane; j < H; j += 32) p += bk[j] * qs[bb][j];
        p = warp_sum(p);
        if (lane == 0) g_cK[b0+bb] = p;
    }
}

// ============ inline reduce for one batch (last-done block runs this) =====
__device__ __noinline__ void reduce_batch(
    int b, int nact,
    float* s_red, float* s_part, float* s_cp, float* s_xsm, float* s_ctx,
    const float* __restrict__ Wv, const float* __restrict__ bv,
    const float* __restrict__ Wmix, const float* __restrict__ bmix,
    const float* __restrict__ lns, const float* __restrict__ lnb)
{
    int tid = threadIdx.x;
    int t = tid & 127, half = tid >> 7;

    if (tid < 128)
        s_red[tid] = (tid < nact) ? g_pl[b*CHUNKS + tid] : 0.f;
    __syncthreads();
    for (int o = 64; o > 0; o >>= 1) {
        if (tid < o) s_red[tid] += s_red[tid+o];
        __syncthreads();
    }
    float L = s_red[0];
    __syncthreads();

    {
        float a = 0.f;
#pragma unroll 4
        for (int c = half; c < nact; c += 2)
            a += g_pacc[((size_t)b*CHUNKS + c)*H + t];
        s_part[tid] = a;
    }
    __syncthreads();
    if (tid < 128) {
        s_cp[t] = (s_part[t] + s_part[t+128]) / L;
        s_xsm[t] = g_x[b*H + t];
    }
    __syncthreads();

    {
        float cv = 0.f;
        int i0 = half*64;
#pragma unroll 8
        for (int i = i0; i < i0 + 64; i++) cv += s_cp[i] * Wv[i*H + t];
        s_part[tid] = cv;
    }
    __syncthreads();
    if (tid < 128) s_ctx[t] = s_part[t] + s_part[t+128] + bv[t];
    __syncthreads();

    {
        float hm = 0.f;
        if (half == 0) {
#pragma unroll 8
            for (int i = 0; i < 128; i++) hm += s_xsm[i] * Wmix[i*H + t];
        } else {
#pragma unroll 8
            for (int i = 0; i < 128; i++) hm += s_ctx[i] * Wmix[(H+i)*H + t];
        }
        s_part[tid] = hm;
    }
    __syncthreads();

    float hv = 0.f;
    if (tid < 128) {
        hv = tanhf(s_part[t] + s_part[t+128] + bmix[t]);
        s_red[t] = hv;
    }
    __syncthreads();
    for (int o = 64; o > 0; o >>= 1) {
        if (tid < o) s_red[tid] += s_red[tid+o];
        __syncthreads();
    }
    float mu = s_red[0] * (1.f/128.f);
    __syncthreads();
    float dv = hv - mu;
    if (tid < 128) s_red[t] = dv*dv;
    __syncthreads();
    for (int o = 64; o > 0; o >>= 1) {
        if (tid < o) s_red[tid] += s_red[tid+o];
        __syncthreads();
    }
    float var = s_red[0] * (1.f/128.f);

    if (tid < 128)
        g_hln[b*H + t] = dv * rsqrtf(var + 1e-6f) * lns[t] + lnb[t];
}

// ==== K2a: ACTIVE region copy + flash pass + inline per-batch reduce ======
// grid (CHUNKS, B); inactive chunks early-exit (handled by k_inactive).
__global__ __launch_bounds__(256) void k_active(
    const float* __restrict__ attn_mem, const int* __restrict__ step_p,
    const float* __restrict__ Wv, const float* __restrict__ bv,
    const float* __restrict__ Wmix, const float* __restrict__ bmix,
    const float* __restrict__ lns, const float* __restrict__ lnb,
    float* __restrict__ out)
{
    __shared__ float sm_acc[8][H];
    __shared__ float sm_l[8];
    __shared__ int sm_last;
    __shared__ float s_red[128], s_part[256], s_cp[H], s_xsm[H], s_ctx[H];

    int b = blockIdx.y;
    int chunk = blockIdx.x;
    int step = *step_p;
    if (chunk*ROWS > step) return;      // inactive -> other kernel

    int tid = threadIdx.x, wid = tid >> 5, lane = tid & 31;
    int base = chunk*ROWS + wid*8;

    const float4* src = (const float4*)(attn_mem + (size_t)b*S*H);
    float4* dst = (float4*)(out + OFF_ATTN + (size_t)b*S*H);
    const float4* xr = (const float4*)(g_x + b*H);
    float4 rf = ((const float4*)(g_r + b*H))[lane];
    float cK = g_cK[b];
    const float scl = 0.08838834764831843f;   // 1/sqrt(128)

    float4 v[8];
#pragma unroll
    for (int t = 0; t < 8; t++) {
        int s = base + t;
        v[t] = (s == step) ? xr[lane] : __ldcs(&src[(size_t)s*32 + lane]);
    }
#pragma unroll
    for (int t = 0; t < 8; t++) __stcs(&dst[(size_t)(base+t)*32 + lane], v[t]);

    // 8 independent partial dots, then 8 interleaved butterfly reductions
    float d[8];
#pragma unroll
    for (int t = 0; t < 8; t++)
        d[t] = v[t].x*rf.x + v[t].y*rf.y + v[t].z*rf.z + v[t].w*rf.w;
#pragma unroll
    for (int o = 16; o > 0; o >>= 1) {
#pragma unroll
        for (int t = 0; t < 8; t++)
            d[t] += __shfl_xor_sync(0xffffffffu, d[t], o);
    }

    // no-max softmax partials: scores are O(1), fp32 exp is safe
    float l = 0.f;
    float4 acc = {0.f, 0.f, 0.f, 0.f};
#pragma unroll
    for (int t = 0; t < 8; t++) {
        float w = (base + t <= step) ? __expf((d[t] + cK) * scl) : 0.f;
        l += w;
        acc.x += w*v[t].x; acc.y += w*v[t].y;
        acc.z += w*v[t].z; acc.w += w*v[t].w;
    }
    ((float4*)sm_acc[wid])[lane] = acc;
    if (lane == 0) sm_l[wid] = l;
    __syncthreads();

    if (tid < H) {
        float a = 0.f;
#pragma unroll
        for (int w = 0; w < 8; w++) a += sm_acc[w][tid];
        g_pacc[((size_t)b*CHUNKS + chunk)*H + tid] = a;
    }
    if (tid == 0) {
        float L = 0.f;
#pragma unroll
        for (int w = 0; w < 8; w++) L += sm_l[w];
        g_pl[b*CHUNKS + chunk] = L;
    }

    int nact = (step >> 6) + 1;
    __threadfence();                 // publish pacc/pl
    __syncthreads();
    if (tid == 0) {
        int old = atomicAdd(&g_cnt[b], 1);
        sm_last = (old == nact - 1);
    }
    __syncthreads();
    if (sm_last) {
        __threadfence();             // acquire
        reduce_batch(b, nact, s_red, s_part, s_cp, s_xsm, s_ctx,
                     Wv, bv, Wmix, bmix, lns, lnb);
    }
}

// ==== K2b: INACTIVE region pure streaming copy (no dependencies) ==========
__global__ __launch_bounds__(256) void k_inactive(
    const float* __restrict__ attn_mem, const int* __restrict__ step_p,
    float* __restrict__ out)
{
    int b = blockIdx.y;
    int chunk = blockIdx.x;
    int step = *step_p;
    if (chunk*ROWS <= step) return;     // active -> other kernel

    int tid = threadIdx.x, wid = tid >> 5, lane = tid & 31;
    int base = chunk*ROWS + wid*8;
    const float4* src = (const float4*)(attn_mem + (size_t)b*S*H);
    float4* dst = (float4*)(out + OFF_ATTN + (size_t)b*S*H);

    float4 v[8];
#pragma unroll
    for (int t = 0; t < 8; t++) v[t] = __ldcs(&src[(size_t)(base+t)*32 + lane]);
#pragma unroll
    for (int t = 0; t < 8; t++) __stcs(&dst[(size_t)(base+t)*32 + lane], v[t]);
}

// ==== K4: logits = h_ln @ Wout + bout; 2 cols (c, c+256) x 16 batches =====
__global__ __launch_bounds__(256, 3) void k_logits(
    const float* __restrict__ Wout, const float* __restrict__ bout,
    float* __restrict__ out)
{
    __shared__ ull hsu[H*8];   // [k][batch-pair]: 8KB
    int tid = threadIdx.x;
    int bq = blockIdx.y;       // batches [bq*16, bq*16+16)
    float* hsf = (float*)hsu;
    for (int idx = tid; idx < 16*H; idx += 256) {
        int k = idx >> 4, bb = idx & 15;
        hsf[k*16 + bb] = g_hln[(bq*16 + bb)*H + k];
    }
    __syncthreads();

    int base = blockIdx.x * 512;
    int ca = base + tid;            // column A
    int cb = ca + 256;              // column B
    int ca_ok = (ca < V), cb_ok = (cb < V);
    int ca_c = ca_ok ? ca : (V-1);
    int cb_c = cb_ok ? cb : (V-1);

    ull acc0[8], acc1[8];
#pragma unroll
    for (int i = 0; i < 8; i++) { acc0[i] = 0ULL; acc1[i] = 0ULL; }

#pragma unroll 4
    for (int k = 0; k < H; k++) {
        float wa = Wout[(size_t)k*V + ca_c];
        float wb = Wout[(size_t)k*V + cb_c];
        ull w2a = bcast2(wa);
        ull w2b = bcast2(wb);
        const ulonglong2* hp = (const ulonglong2*)(hsu + k*8);
#pragma unroll
        for (int p = 0; p < 4; p++) {
            ulonglong2 hv = hp[p];
            acc0[2*p]   = fma2(hv.x, w2a, acc0[2*p]);
            acc0[2*p+1] = fma2(hv.y, w2a, acc0[2*p+1]);
            acc1[2*p]   = fma2(hv.x, w2b, acc1[2*p]);
            acc1[2*p+1] = fma2(hv.y, w2b, acc1[2*p+1]);
        }
    }

    if (ca_ok) {
        float bo = bout[ca_c];
#pragma unroll
        for (int p = 0; p < 8; p++) {
            float f0, f1;
            asm("mov.b64 {%0, %1}, %2;" : "=f"(f0), "=f"(f1) : "l"(acc0[p]));
            int b0r = bq*16 + 2*p;
            out[(size_t)b0r*V + ca]     = f0 + bo;
            out[(size_t)(b0r+1)*V + ca] = f1 + bo;
        }
    }
    if (cb_ok) {
        float bo = bout[cb_c];
#pragma unroll
        for (int p = 0; p < 8; p++) {
            float f0, f1;
            asm("mov.b64 {%0, %1}, %2;" : "=f"(f0), "=f"(f1) : "l"(acc1[p]));
            int b0r = bq*16 + 2*p;
            out[(size_t)b0r*V + cb]     = f0 + bo;
            out[(size_t)(b0r+1)*V + cb] = f1 + bo;
        }
    }
}

// ---------------- streams/events created at static-init -------------------
static cudaStream_t g_hi, g_lo;
static cudaEvent_t  g_fork, g_join_hi, g_join_lo;
static struct StreamInit {
    StreamInit() {
        int least, greatest;
        cudaDeviceGetStreamPriorityRange(&least, &greatest);
        cudaStreamCreateWithPriority(&g_hi, cudaStreamNonBlocking, greatest);
        cudaStreamCreateWithPriority(&g_lo, cudaStreamNonBlocking, least);
        cudaEventCreateWithFlags(&g_fork, cudaEventDisableTiming);
        cudaEventCreateWithFlags(&g_join_hi, cudaEventDisableTiming);
        cudaEventCreateWithFlags(&g_join_lo, cudaEventDisableTiming);
    }
} g_stream_init;

// ==========================================================================
extern "C" void kernel_launch(void* const* d_in, const int* in_sizes, int n_in,
                              void* d_out, int out_size)
{
    const int*   token_id = (const int*)  d_in[0];
    const float* c0       = (const float*)d_in[1];
    const float* h0       = (const float*)d_in[2];
    const float* attn_mem = (const float*)d_in[3];
    const int*   step_p   = (const int*)  d_in[4];
    const float* emb      = (const float*)d_in[5];
    const float* Wi       = (const float*)d_in[6];
    const float* Uh       = (const float*)d_in[7];
    const float* bL       = (const float*)d_in[8];
    const float* Wq       = (const float*)d_in[9];
    const float* bq       = (const float*)d_in[10];
    const float* Wk       = (const float*)d_in[11];
    const float* bk       = (const float*)d_in[12];
    const float* Wv       = (const float*)d_in[13];
    const float* bv       = (const float*)d_in[14];
    const float* Wmix     = (const float*)d_in[15];
    const float* bmix     = (const float*)d_in[16];
    const float* lns      = (const float*)d_in[17];
    const float* lnb      = (const float*)d_in[18];
    const float* Wout     = (const float*)d_in[19];
    const float* bout     = (const float*)d_in[20];
    float* out = (float*)d_out;

    dim3 g2(CHUNKS, B);
    dim3 g4((V + 511)/512, 4);

    // fork both worker streams off the capture stream
    cudaEventRecord(g_fork, 0);
    cudaStreamWaitEvent(g_lo, g_fork, 0);
    cudaStreamWaitEvent(g_hi, g_fork, 0);

    // LOW priority: inactive-region copy (no deps; soaks idle bandwidth)
    k_inactive<<<g2, 256, 0, g_lo>>>(attn_mem, step_p, out);
    cudaEventRecord(g_join_lo, g_lo);

    // HIGH priority: lstm -> active copy+flash(+reduce) -> logits
    k_lstm<<<32, 256, 0, g_hi>>>(token_id, c0, h0, emb, Wi, Uh, bL,
                                 Wq, bq, Wk, bk, out);
    k_active<<<g2, 256, 0, g_hi>>>(attn_mem, step_p, Wv, bv, Wmix, bmix,
                                   lns, lnb, out);
    k_logits<<<g4, 256, 0, g_hi>>>(Wout, bout, out);
    cudaEventRecord(g_join_hi, g_hi);

    // join both chains back onto the capture stream
    cudaStreamWaitEvent(0, g_join_lo, 0);
    cudaStreamWaitEvent(0, g_join_hi, 0);
}

// round 15
// speedup vs baseline: 1.7334x; 1.3332x over previous
#include <cuda_runtime.h>
#include <math.h>

#define B 64
#define H 128
#define E 128
#define NL 4
#define S 8192
#define V 50257
#define FOURH 512
#define CHUNKS 128   // S / ROWS
#define ROWS 64

#define SZ_LOGITS (B*V)
#define OFF_C  (SZ_LOGITS)
#define OFF_H  (OFF_C + NL*B*H)
#define OFF_ATTN (OFF_H + NL*B*H)

typedef unsigned long long ull;

// ---------------- device scratch (no allocations allowed) ----------------
__device__ __align__(16) float g_x[B*H];          // final hidden (x)
__device__ __align__(16) float g_r[B*H];          // Wk @ q  per batch
__device__ float g_cK[B];                          // bk . q
__device__ float g_pl[B*CHUNKS];                   // partial exp-sums
__device__ __align__(16) float g_pacc[B*CHUNKS*H]; // partial weighted sums
__device__ __align__(16) float g_hln[B*H];
__device__ int g_cnt[B];                           // per-batch done counters
__device__ int g_done = 0;                         // LSTM blocks finished

__device__ __forceinline__ float warp_sum(float v) {
#pragma unroll
    for (int o = 16; o > 0; o >>= 1) v += __shfl_xor_sync(0xffffffffu, v, o);
    return v;
}
__device__ __forceinline__ float sigf(float x) { return 1.f / (1.f + __expf(-x)); }

__device__ __forceinline__ ull fma2(ull a, ull b, ull c) {
    ull d;
    asm("fma.rn.f32x2 %0, %1, %2, %3;" : "=l"(d) : "l"(a), "l"(b), "l"(c));
    return d;
}
__device__ __forceinline__ ull bcast2(float f) {
    ull d;
    asm("mov.b64 %0, {%1, %1};" : "=l"(d) : "f"(f));
    return d;
}

// ---------------- shared-memory role layouts (16B-aligned union) ----------
struct __align__(16) LstmSmem {
    ull xs2[2][H];
    ull hs2[2][H];
    float gp[2][2][FOURH];
    float qs[2][H];
};
struct __align__(16) FlashSmem {
    float acc[8][H];
    float l[8];
    float red[128], part[256], cp[H], xsm[H], ctx[H];
};

// ============ LSTM role: embed + 4 layers + q, r = Wk@q, cK = bk.q ========
// Resets g_cnt for its 2 batches BEFORE releasing g_done.
__device__ void lstm_role(
    LstmSmem& sm, int b0,
    const int* __restrict__ token_id, const float* __restrict__ c0,
    const float* __restrict__ h0, const float* __restrict__ emb,
    const float* __restrict__ Wi, const float* __restrict__ Uh,
    const float* __restrict__ bL, const float* __restrict__ Wq,
    const float* __restrict__ bq, const float* __restrict__ Wk,
    const float* __restrict__ bk, float* __restrict__ out)
{
    int tid = threadIdx.x;

    if (tid == 0) { g_cnt[b0] = 0; g_cnt[b0+1] = 0; }

    for (int idx = tid; idx < 2*H; idx += 256) {
        int bb = idx >> 7, i = idx & 127;
        float v = emb[(size_t)token_id[b0+bb]*E + i];
        sm.xs2[bb][i] = bcast2(v);
    }

    int khalf = tid >> 7;        // 0 or 1: which half of k
    int tc = tid & 127;          // column group: cols [4tc, 4tc+4)
    int cbase = tc * 4;

    for (int l = 0; l < NL; l++) {
        for (int idx = tid; idx < 2*H; idx += 256) {
            int bb = idx >> 7, i = idx & 127;
            float v = h0[((size_t)l*B + b0 + bb)*H + i];
            sm.hs2[bb][i] = bcast2(v);
        }
        __syncthreads();

        ull a00 = 0, a01 = 0, a10 = 0, a11 = 0;
        const ulonglong2* Wi2 = (const ulonglong2*)(Wi + (size_t)l*E*FOURH);
        const ulonglong2* Uh2 = (const ulonglong2*)(Uh + (size_t)l*H*FOURH);
        int k0 = khalf * 64;
#pragma unroll 4
        for (int k = k0; k < k0 + 64; k++) {
            ulonglong2 w = Wi2[k*(FOURH/4) + tc];
            ulonglong2 u = Uh2[k*(FOURH/4) + tc];
            ull x0 = sm.xs2[0][k], x1 = sm.xs2[1][k];
            ull hh0 = sm.hs2[0][k], hh1 = sm.hs2[1][k];
            a00 = fma2(w.x, x0, a00);  a01 = fma2(w.y, x0, a01);
            a00 = fma2(u.x, hh0, a00); a01 = fma2(u.y, hh0, a01);
            a10 = fma2(w.x, x1, a10);  a11 = fma2(w.y, x1, a11);
            a10 = fma2(u.x, hh1, a10); a11 = fma2(u.y, hh1, a11);
        }
        *(ull*)&sm.gp[khalf][0][cbase]   = a00;
        *(ull*)&sm.gp[khalf][0][cbase+2] = a01;
        *(ull*)&sm.gp[khalf][1][cbase]   = a10;
        *(ull*)&sm.gp[khalf][1][cbase+2] = a11;
        __syncthreads();

        // activations: 256 outputs (2 batches x 128)
        {
            int bb = tid >> 7, i = tid & 127;
            const float* bb_l = bL + l*FOURH;
            float ig = sm.gp[0][bb][i]       + sm.gp[1][bb][i]       + bb_l[i];
            float fg = sm.gp[0][bb][128 + i] + sm.gp[1][bb][128 + i] + bb_l[128 + i];
            float gg = sm.gp[0][bb][256 + i] + sm.gp[1][bb][256 + i] + bb_l[256 + i];
            float og = sm.gp[0][bb][384 + i] + sm.gp[1][bb][384 + i] + bb_l[384 + i];
            size_t ofs = ((size_t)l*B + b0 + bb)*H + i;
            float cprev = c0[ofs];
            float cn = sigf(fg)*cprev + sigf(ig)*tanhf(gg);
            float hn = sigf(og)*tanhf(cn);
            out[OFF_C + ofs] = cn;
            out[OFF_H + ofs] = hn;
            sm.xs2[bb][i] = bcast2(hn);   // guarded by sync at loop top
        }
    }
    __syncthreads();

    for (int idx = tid; idx < 2*H; idx += 256) {
        int bb = idx >> 7, i = idx & 127;
        g_x[(b0+bb)*H + i] = ((const float2*)&sm.xs2[bb][i])->x;
    }

    // q[bb][j] = x . Wq[:,j] + bq[j]
    {
        int bb = tid >> 7, j = tid & 127;
        float acc = bq[j];
#pragma unroll 8
        for (int i = 0; i < H; i++)
            acc += ((const float2*)&sm.xs2[bb][i])->x * Wq[i*H + j];
        sm.qs[bb][j] = acc;
    }
    __syncthreads();

    // r[bb][i] = Wk[i,:] . q[bb]  (warp per row)
    int wid = tid >> 5, lane = tid & 31;
    for (int row = wid; row < 2*H; row += 8) {
        int bb = row >> 7, i = row & 127;
        float4 wv = ((const float4*)(Wk + (size_t)i*H))[lane];
        float4 qv = ((const float4*)sm.qs[bb])[lane];
        float d = wv.x*qv.x + wv.y*qv.y + wv.z*qv.z + wv.w*qv.w;
        d = warp_sum(d);
        if (lane == 0) g_r[(b0+bb)*H + i] = d;
    }
    if (wid < 2) {
        int bb = wid;
        float p = 0.f;
        for (int j = lane; j < H; j += 32) p += bk[j] * sm.qs[bb][j];
        p = warp_sum(p);
        if (lane == 0) g_cK[b0+bb] = p;
    }
    __syncthreads();
    __threadfence();                    // release g_x/g_r/g_cK/g_cnt
    if (tid == 0) atomicAdd(&g_done, 1);
}

// ============ inline reduce for one batch (last-done block runs this) =====
__device__ __noinline__ void reduce_batch(
    int b, int nact, FlashSmem& s,
    const float* __restrict__ Wv, const float* __restrict__ bv,
    const float* __restrict__ Wmix, const float* __restrict__ bmix,
    const float* __restrict__ lns, const float* __restrict__ lnb)
{
    int tid = threadIdx.x;
    int t = tid & 127, half = tid >> 7;

    if (tid < 128)
        s.red[tid] = (tid < nact) ? g_pl[b*CHUNKS + tid] : 0.f;
    __syncthreads();
    for (int o = 64; o > 0; o >>= 1) {
        if (tid < o) s.red[tid] += s.red[tid+o];
        __syncthreads();
    }
    float L = s.red[0];
    __syncthreads();

    {
        float a = 0.f;
#pragma unroll 4
        for (int c = half; c < nact; c += 2)
            a += g_pacc[((size_t)b*CHUNKS + c)*H + t];
        s.part[tid] = a;
    }
    __syncthreads();
    if (tid < 128) {
        s.cp[t] = (s.part[t] + s.part[t+128]) / L;
        s.xsm[t] = g_x[b*H + t];
    }
    __syncthreads();

    {
        float cv = 0.f;
        int i0 = half*64;
#pragma unroll 8
        for (int i = i0; i < i0 + 64; i++) cv += s.cp[i] * Wv[i*H + t];
        s.part[tid] = cv;
    }
    __syncthreads();
    if (tid < 128) s.ctx[t] = s.part[t] + s.part[t+128] + bv[t];
    __syncthreads();

    {
        float hm = 0.f;
        if (half == 0) {
#pragma unroll 8
            for (int i = 0; i < 128; i++) hm += s.xsm[i] * Wmix[i*H + t];
        } else {
#pragma unroll 8
            for (int i = 0; i < 128; i++) hm += s.ctx[i] * Wmix[(H+i)*H + t];
        }
        s.part[tid] = hm;
    }
    __syncthreads();

    float hv = 0.f;
    if (tid < 128) {
        hv = tanhf(s.part[t] + s.part[t+128] + bmix[t]);
        s.red[t] = hv;
    }
    __syncthreads();
    for (int o = 64; o > 0; o >>= 1) {
        if (tid < o) s.red[tid] += s.red[tid+o];
        __syncthreads();
    }
    float mu = s.red[0] * (1.f/128.f);
    __syncthreads();
    float dv = hv - mu;
    if (tid < 128) s.red[t] = dv*dv;
    __syncthreads();
    for (int o = 64; o > 0; o >>= 1) {
        if (tid < o) s.red[tid] += s.red[tid+o];
        __syncthreads();
    }
    float var = s.red[0] * (1.f/128.f);

    if (tid < 128)
        g_hln[b*H + t] = dv * rsqrtf(var + 1e-6f) * lns[t] + lnb[t];
}

// ==== MEGA: [32 LSTM blocks] + [8192 copy / copy+flash(+reduce) blocks] ===
// 1-D grid, id-ordered dispatch:
//   id in [0,32): LSTM for batches (2id, 2id+1); sets g_done.
//   id >= 32: w = id-32; b = w&63; chunk = 127-(w>>6).
//     inactive chunk (scheduled FIRST) -> pure streaming copy (hides LSTM)
//     active chunk (scheduled last)    -> spin-once on g_done, fused
//       copy + no-max flash partials; last-done block per batch reduces.
__global__ __launch_bounds__(256) void k_mega(
    const float* __restrict__ attn_mem, const int* __restrict__ step_p,
    const int* __restrict__ token_id, const float* __restrict__ c0,
    const float* __restrict__ h0, const float* __restrict__ emb,
    const float* __restrict__ Wi, const float* __restrict__ Uh,
    const float* __restrict__ bL, const float* __restrict__ Wq,
    const float* __restrict__ bq, const float* __restrict__ Wk,
    const float* __restrict__ bk,
    const float* __restrict__ Wv, const float* __restrict__ bv,
    const float* __restrict__ Wmix, const float* __restrict__ bmix,
    const float* __restrict__ lns, const float* __restrict__ lnb,
    float* __restrict__ out)
{
    __shared__ __align__(16) union { LstmSmem lstm; FlashSmem fl; } sm;
    __shared__ int sm_last;

    int id = blockIdx.x;
    int tid = threadIdx.x, wid = tid >> 5, lane = tid & 31;

    if (id < 32) {
        lstm_role(sm.lstm, id*2, token_id, c0, h0, emb, Wi, Uh, bL,
                  Wq, bq, Wk, bk, out);
        return;
    }

    int w = id - 32;
    int b = w & 63;
    int chunk = 127 - (w >> 6);    // inactive (high) chunks get low ids
    int step = *step_p;
    int base = chunk*ROWS + wid*8;

    const float4* src = (const float4*)(attn_mem + (size_t)b*S*H);
    float4* dst = (float4*)(out + OFF_ATTN + (size_t)b*S*H);

    if (chunk*ROWS > step) {
        // pure copy: streaming loads/stores, no L2 retention
        float4 v[8];
#pragma unroll
        for (int t = 0; t < 8; t++) v[t] = __ldcs(&src[(size_t)(base+t)*32 + lane]);
#pragma unroll
        for (int t = 0; t < 8; t++) __stcs(&dst[(size_t)(base+t)*32 + lane], v[t]);
        return;
    }

    // ---- active: wait for LSTM results (free by schedule order) ----
    if (tid == 0) {
        int fv;
        do {
            asm volatile("ld.global.cg.b32 %0, [%1];" : "=r"(fv) : "l"(&g_done));
            if (fv < 32) __nanosleep(64);
        } while (fv < 32);
    }
    __syncthreads();
    __threadfence();               // acquire

    float4 rf;
    {
        const float* rp = g_r + b*H + lane*4;
        rf.x = __ldcg(rp); rf.y = __ldcg(rp+1); rf.z = __ldcg(rp+2); rf.w = __ldcg(rp+3);
    }
    float cK = __ldcg(&g_cK[b]);
    const float scl = 0.08838834764831843f;   // 1/sqrt(128)

    float4 v[8];
#pragma unroll
    for (int t = 0; t < 8; t++) {
        int s = base + t;
        if (s == step) {
            const float* xp = g_x + b*H + lane*4;
            v[t].x = __ldcg(xp); v[t].y = __ldcg(xp+1);
            v[t].z = __ldcg(xp+2); v[t].w = __ldcg(xp+3);
        } else {
            v[t] = __ldcs(&src[(size_t)s*32 + lane]);
        }
    }
#pragma unroll
    for (int t = 0; t < 8; t++) __stcs(&dst[(size_t)(base+t)*32 + lane], v[t]);

    // 8 independent partial dots, then 8 interleaved butterfly reductions
    float d[8];
#pragma unroll
    for (int t = 0; t < 8; t++)
        d[t] = v[t].x*rf.x + v[t].y*rf.y + v[t].z*rf.z + v[t].w*rf.w;
#pragma unroll
    for (int o = 16; o > 0; o >>= 1) {
#pragma unroll
        for (int t = 0; t < 8; t++)
            d[t] += __shfl_xor_sync(0xffffffffu, d[t], o);
    }

    // no-max softmax partials: scores are O(1), fp32 exp is safe
    float l = 0.f;
    float4 acc = {0.f, 0.f, 0.f, 0.f};
#pragma unroll
    for (int t = 0; t < 8; t++) {
        float ww = (base + t <= step) ? __expf((d[t] + cK) * scl) : 0.f;
        l += ww;
        acc.x += ww*v[t].x; acc.y += ww*v[t].y;
        acc.z += ww*v[t].z; acc.w += ww*v[t].w;
    }
    ((float4*)sm.fl.acc[wid])[lane] = acc;
    if (lane == 0) sm.fl.l[wid] = l;
    __syncthreads();

    if (tid < H) {
        float a = 0.f;
#pragma unroll
        for (int ww = 0; ww < 8; ww++) a += sm.fl.acc[ww][tid];
        g_pacc[((size_t)b*CHUNKS + chunk)*H + tid] = a;
    }
    if (tid == 0) {
        float L = 0.f;
#pragma unroll
        for (int ww = 0; ww < 8; ww++) L += sm.fl.l[ww];
        g_pl[b*CHUNKS + chunk] = L;
    }

    // last-done block for this batch runs the reduce inline
    int nact = (step >> 6) + 1;
    __threadfence();               // publish pacc/pl
    __syncthreads();
    if (tid == 0) {
        int old = atomicAdd(&g_cnt[b], 1);
        sm_last = (old == nact - 1);
    }
    __syncthreads();
    if (sm_last) {
        __threadfence();           // acquire all blocks' partials
        reduce_batch(b, nact, sm.fl, Wv, bv, Wmix, bmix, lns, lnb);
    }
}

// ==== K4: logits = h_ln @ Wout + bout; 2 cols (c, c+256) x 16 batches =====
// Also resets g_done for the next graph replay (runs after k_mega).
__global__ __launch_bounds__(256, 3) void k_logits(
    const float* __restrict__ Wout, const float* __restrict__ bout,
    float* __restrict__ out)
{
    __shared__ __align__(16) ull hsu[H*8];   // [k][batch-pair]: 8KB
    int tid = threadIdx.x;
    int bq = blockIdx.y;       // batches [bq*16, bq*16+16)

    if (blockIdx.x == 0 && bq == 0 && tid == 0) g_done = 0;

    float* hsf = (float*)hsu;
    for (int idx = tid; idx < 16*H; idx += 256) {
        int k = idx >> 4, bb = idx & 15;
        hsf[k*16 + bb] = g_hln[(bq*16 + bb)*H + k];
    }
    __syncthreads();

    int base = blockIdx.x * 512;
    int ca = base + tid;            // column A
    int cb = ca + 256;              // column B
    int ca_ok = (ca < V), cb_ok = (cb < V);
    int ca_c = ca_ok ? ca : (V-1);
    int cb_c = cb_ok ? cb : (V-1);

    ull acc0[8], acc1[8];
#pragma unroll
    for (int i = 0; i < 8; i++) { acc0[i] = 0ULL; acc1[i] = 0ULL; }

#pragma unroll 4
    for (int k = 0; k < H; k++) {
        float wa = Wout[(size_t)k*V + ca_c];
        float wb = Wout[(size_t)k*V + cb_c];
        ull w2a = bcast2(wa);
        ull w2b = bcast2(wb);
        const ulonglong2* hp = (const ulonglong2*)(hsu + k*8);
#pragma unroll
        for (int p = 0; p < 4; p++) {
            ulonglong2 hv = hp[p];
            acc0[2*p]   = fma2(hv.x, w2a, acc0[2*p]);
            acc0[2*p+1] = fma2(hv.y, w2a, acc0[2*p+1]);
            acc1[2*p]   = fma2(hv.x, w2b, acc1[2*p]);
            acc1[2*p+1] = fma2(hv.y, w2b, acc1[2*p+1]);
        }
    }

    if (ca_ok) {
        float bo = bout[ca_c];
#pragma unroll
        for (int p = 0; p < 8; p++) {
            float f0, f1;
            asm("mov.b64 {%0, %1}, %2;" : "=f"(f0), "=f"(f1) : "l"(acc0[p]));
            int b0r = bq*16 + 2*p;
            out[(size_t)b0r*V + ca]     = f0 + bo;
            out[(size_t)(b0r+1)*V + ca] = f1 + bo;
        }
    }
    if (cb_ok) {
        float bo = bout[cb_c];
#pragma unroll
        for (int p = 0; p < 8; p++) {
            float f0, f1;
            asm("mov.b64 {%0, %1}, %2;" : "=f"(f0), "=f"(f1) : "l"(acc1[p]));
            int b0r = bq*16 + 2*p;
            out[(size_t)b0r*V + cb]     = f0 + bo;
            out[(size_t)(b0r+1)*V + cb] = f1 + bo;
        }
    }
}

// ==========================================================================
extern "C" void kernel_launch(void* const* d_in, const int* in_sizes, int n_in,
                              void* d_out, int out_size)
{
    const int*   token_id = (const int*)  d_in[0];
    const float* c0       = (const float*)d_in[1];
    const float* h0       = (const float*)d_in[2];
    const float* attn_mem = (const float*)d_in[3];
    const int*   step_p   = (const int*)  d_in[4];
    const float* emb      = (const float*)d_in[5];
    const float* Wi       = (const float*)d_in[6];
    const float* Uh       = (const float*)d_in[7];
    const float* bL       = (const float*)d_in[8];
    const float* Wq       = (const float*)d_in[9];
    const float* bq       = (const float*)d_in[10];
    const float* Wk       = (const float*)d_in[11];
    const float* bk       = (const float*)d_in[12];
    const float* Wv       = (const float*)d_in[13];
    const float* bv       = (const float*)d_in[14];
    const float* Wmix     = (const float*)d_in[15];
    const float* bmix     = (const float*)d_in[16];
    const float* lns      = (const float*)d_in[17];
    const float* lnb      = (const float*)d_in[18];
    const float* Wout     = (const float*)d_in[19];
    const float* bout     = (const float*)d_in[20];
    float* out = (float*)d_out;

    k_mega<<<32 + CHUNKS*B, 256>>>(attn_mem, step_p, token_id, c0, h0, emb,
                                   Wi, Uh, bL, Wq, bq, Wk, bk,
                                   Wv, bv, Wmix, bmix, lns, lnb, out);
    dim3 g4((V + 511)/512, 4);
    k_logits<<<g4, 256>>>(Wout, bout, out);
}